// round 8
// baseline (speedup 1.0000x reference)
#include <cuda_runtime.h>
#include <cuda_bf16.h>
#include <cstdint>
#include <cstddef>

#define N_NODES 50000
#define FEAT 128
#define E_MAX 800000
#define WSTRIDE 136   // bf16 elements per row in smem (272B = 17 * 16B -> conflict-free ldmatrix)

// ---------------- scratch (static device globals; no allocs) ----------------
__device__ __align__(16) unsigned char g_needed[N_NODES];
__device__ int                         g_cnt[N_NODES];
__device__ __align__(16) float         g_accT[(size_t)N_NODES * FEAT];
__device__ __align__(16) float         g_T[(size_t)N_NODES * FEAT];
__device__ int                         g_is64;
__device__ int                         g_nact;
__device__ __align__(8)  int2          g_ec[E_MAX];                 // compacted edges
__device__ __align__(16) unsigned short g_Whi[128 * WSTRIDE];       // W1^T hi, padded [n][k]
__device__ __align__(16) unsigned short g_Wlo[128 * WSTRIDE];       // W1^T lo, padded [n][k]

__device__ __forceinline__ uint32_t smem_u32(const void* p) {
    uint32_t a;
    asm("{ .reg .u64 t; cvta.to.shared.u64 t, %1; cvt.u32.u64 %0, t; }" : "=r"(a) : "l"(p));
    return a;
}

#define LDSM4(r, addr) \
    asm volatile("ldmatrix.sync.aligned.m8n8.x4.shared.b16 {%0,%1,%2,%3}, [%4];" \
        : "=r"((r)[0]), "=r"((r)[1]), "=r"((r)[2]), "=r"((r)[3]) : "r"(addr))

#define MMA16816(d, a, b0, b1) \
    asm volatile("mma.sync.aligned.m16n8k16.row.col.f32.bf16.bf16.f32 " \
        "{%0,%1,%2,%3}, {%4,%5,%6,%7}, {%8,%9}, {%0,%1,%2,%3};" \
        : "+f"((d)[0]), "+f"((d)[1]), "+f"((d)[2]), "+f"((d)[3]) \
        : "r"((a)[0]), "r"((a)[1]), "r"((a)[2]), "r"((a)[3]), "r"(b0), "r"(b1))

// ---------------------------------------------------------------------------
// Probe index dtype; also zero g_nact for this call.
// ---------------------------------------------------------------------------
__global__ void probe_kernel(const int* __restrict__ e, int nwords)
{
    int lane = threadIdx.x;
    int n = nwords < 2048 ? nwords : 2048;
    int any = 0;
    for (int i = 1 + 2 * lane; i < n; i += 64) any |= e[i];
    #pragma unroll
    for (int o = 16; o; o >>= 1) any |= __shfl_xor_sync(0xffffffffu, any, o);
    if (lane == 0) { g_is64 = (any == 0) ? 1 : 0; g_nact = 0; }
}

// ---------------------------------------------------------------------------
// Mark needed nodes + zero their cnt and accT row (one warp per node_idx).
// ---------------------------------------------------------------------------
__global__ __launch_bounds__(256)
void mark_zero_kernel(const void* __restrict__ node_idx, int B)
{
    int w    = (blockIdx.x * blockDim.x + threadIdx.x) >> 5;
    int lane = threadIdx.x & 31;
    if (w >= B) return;
    long long s = g_is64 ? ((const long long*)node_idx)[w]
                         : (long long)((const int*)node_idx)[w];
    if ((unsigned long long)s >= (unsigned long long)N_NODES) return;
    if (lane == 0) { g_needed[s] = 1; g_cnt[s] = 0; }
    *(float4*)&g_accT[(size_t)s * FEAT + lane * 4] = make_float4(0.f, 0.f, 0.f, 0.f);
}

// ---------------------------------------------------------------------------
// Filter + compact edges; count degrees for needed src.
// ---------------------------------------------------------------------------
__global__ __launch_bounds__(256)
void filter_kernel(const void* __restrict__ edges, const int* __restrict__ ind_ptr, int E)
{
    int i    = blockIdx.x * blockDim.x + threadIdx.x;
    int lane = threadIdx.x & 31;
    int is64 = g_is64;
    int keep_self = (*ind_ptr < 2);

    int src = 0, dst = 0;
    bool act = false;
    if (i < E) {
        if (is64) { longlong2 p = ((const longlong2*)edges)[i]; src = (int)p.x; dst = (int)p.y; }
        else      { int2 p = ((const int2*)edges)[i];           src = p.x;      dst = p.y; }
        act = ((src != dst) | keep_self)
              && ((unsigned)src < (unsigned)N_NODES)
              && ((unsigned)dst < (unsigned)N_NODES)
              && g_needed[src];
    }
    unsigned m = __ballot_sync(0xffffffffu, act);
    int cnt = __popc(m);
    int base = 0;
    if (lane == 0 && cnt) base = atomicAdd(&g_nact, cnt);
    base = __shfl_sync(0xffffffffu, base, 0);
    if (act) {
        int off = __popc(m & ((1u << lane) - 1u));
        g_ec[base + off] = make_int2(src, dst);
        atomicAdd(&g_cnt[src], 1);
    }
}

// ---------------------------------------------------------------------------
// W prep: W1^T split into bf16 hi/lo, padded [n][WSTRIDE] k-major layout.
// ---------------------------------------------------------------------------
__global__ void wprep_kernel(const float* __restrict__ W1)
{
    int idx = blockIdx.x * blockDim.x + threadIdx.x;
    if (idx >= 16384) return;
    int n = idx >> 7, k = idx & 127;
    float w = W1[k * 128 + n];
    __nv_bfloat16 hi = __float2bfloat16(w);
    __nv_bfloat16 lo = __float2bfloat16(w - __bfloat162float(hi));
    unsigned short hs, ls;
    *(__nv_bfloat16*)&hs = hi;
    *(__nv_bfloat16*)&ls = lo;
    g_Whi[n * WSTRIDE + k] = hs;
    g_Wlo[n * WSTRIDE + k] = ls;
}

// ---------------------------------------------------------------------------
// GEMM1 via mma.sync (HMMA bf16, 3-pass split): T = tanh(X @ W1 + b1).
// CTA: 256 threads / 8 warps; tile 128 rows x 128 cols; K=128 in smem.
// Warp w owns rows w*16 .. w*16+15 (full 128 cols).
// ---------------------------------------------------------------------------
#define SM_XHI 0
#define SM_XLO (SM_XHI + 128 * WSTRIDE * 2)
#define SM_WHI (SM_XLO + 128 * WSTRIDE * 2)
#define SM_WLO (SM_WHI + 128 * WSTRIDE * 2)
#define SM_TOT (SM_WLO + 128 * WSTRIDE * 2)

__global__ __launch_bounds__(256)
void gemm1_mma_kernel(const float* __restrict__ X,
                      const float* __restrict__ b1,
                      int Nrows)
{
    extern __shared__ char smem[];
    uint32_t sb  = smem_u32(smem);
    int tid  = threadIdx.x;
    int wid  = tid >> 5;
    int lane = tid & 31;
    int row0 = blockIdx.x * 128;

    // --- copy pre-split W images (linear, 16B chunks; 34816B each) ---
    for (int i = tid * 16; i < 128 * WSTRIDE * 2; i += 256 * 16) {
        *(uint4*)(smem + SM_WHI + i) = *(const uint4*)((const char*)g_Whi + i);
        *(uint4*)(smem + SM_WLO + i) = *(const uint4*)((const char*)g_Wlo + i);
    }

    // --- convert X tile fp32 -> bf16 hi/lo, padded [row][WSTRIDE] ---
    {
        int r    = tid >> 1;
        int half = (tid & 1) * 64;
        int gr   = row0 + r;
        const float* xr = X + (size_t)gr * FEAT;
        #pragma unroll
        for (int j = 0; j < 8; j++) {
            int c0 = half + j * 8;
            float4 v0 = make_float4(0.f, 0.f, 0.f, 0.f), v1 = v0;
            if (gr < Nrows) {
                v0 = *(const float4*)&xr[c0];
                v1 = *(const float4*)&xr[c0 + 4];
            }
            float xs[8] = {v0.x, v0.y, v0.z, v0.w, v1.x, v1.y, v1.z, v1.w};
            unsigned hi[4], lo[4];
            #pragma unroll
            for (int q = 0; q < 4; q++) {
                float a = xs[2 * q], b = xs[2 * q + 1];
                __nv_bfloat162 h = __floats2bfloat162_rn(a, b);
                float2 hf = __bfloat1622float2(h);
                __nv_bfloat162 l = __floats2bfloat162_rn(a - hf.x, b - hf.y);
                hi[q] = *(unsigned*)&h;
                lo[q] = *(unsigned*)&l;
            }
            int off = (r * WSTRIDE + c0) * 2;   // 16B aligned (272*r + 16*j')
            *(uint4*)(smem + SM_XHI + off) = make_uint4(hi[0], hi[1], hi[2], hi[3]);
            *(uint4*)(smem + SM_XLO + off) = make_uint4(lo[0], lo[1], lo[2], lo[3]);
        }
    }
    __syncthreads();

    // --- fragment address bases ---
    // A (per warp, 16x16 per k-step): groups of 8 lanes -> tiles
    //   g0: (m0-7, k0-7)  g1: (m8-15, k0-7)  g2: (m0-7, k8-15)  g3: (m8-15, k8-15)
    int sub = lane >> 3, rr = lane & 7;
    int a_m = wid * 16 + (sub & 1) * 8 + rr;
    int a_k = (sub >> 1) * 8;
    uint32_t aOff = (uint32_t)((a_m * WSTRIDE + a_k) * 2);
    // B (16k x 16n per ldsm.x4): g0:(n0-7,k0-7) g1:(n0-7,k8-15) g2:(n8-15,k0-7) g3:(n8-15,k8-15)
    int b_n = (sub >> 1) * 8 + rr;
    int b_k = (sub & 1) * 8;
    uint32_t bOff = (uint32_t)((b_n * WSTRIDE + b_k) * 2);

    float d[16][4];
    #pragma unroll
    for (int j = 0; j < 16; j++)
        #pragma unroll
        for (int q = 0; q < 4; q++) d[j][q] = 0.f;

    #pragma unroll
    for (int pass = 0; pass < 3; pass++) {
        uint32_t aBase = sb + ((pass < 2)  ? SM_XHI : SM_XLO) + aOff;
        uint32_t bBase = sb + ((pass == 1) ? SM_WLO : SM_WHI) + bOff;
        #pragma unroll
        for (int ks = 0; ks < 8; ks++) {
            uint32_t a[4];
            LDSM4(a, aBase + ks * 32);          // k0 = ks*16 -> 32 bytes
            #pragma unroll
            for (int np = 0; np < 8; np++) {
                uint32_t b[4];
                LDSM4(b, bBase + (uint32_t)((np * 16 * WSTRIDE + ks * 16) * 2));
                MMA16816(d[np * 2],     a, b[0], b[1]);
                MMA16816(d[np * 2 + 1], a, b[2], b[3]);
            }
        }
    }

    // --- epilogue: bias + tanh, store to g_T ---
    {
        int g = lane >> 2, c = lane & 3;
        int m0 = wid * 16 + g;
        int gr0 = row0 + m0, gr1 = gr0 + 8;
        #pragma unroll
        for (int j = 0; j < 16; j++) {
            int col = j * 8 + c * 2;
            float bx = b1[col], by = b1[col + 1];
            if (gr0 < Nrows) {
                float2 o;
                o.x = tanhf(d[j][0] + bx);
                o.y = tanhf(d[j][1] + by);
                *(float2*)&g_T[(size_t)gr0 * FEAT + col] = o;
            }
            if (gr1 < Nrows) {
                float2 o;
                o.x = tanhf(d[j][2] + bx);
                o.y = tanhf(d[j][3] + by);
                *(float2*)&g_T[(size_t)gr1 * FEAT + col] = o;
            }
        }
    }
}

// ---------------------------------------------------------------------------
// Aggregate compacted edges: one warp per edge; lane handles 4 floats.
// ---------------------------------------------------------------------------
__global__ __launch_bounds__(256)
void agg_kernel()
{
    int gw   = (blockIdx.x * blockDim.x + threadIdx.x) >> 5;
    int lane = threadIdx.x & 31;
    int nw   = (gridDim.x * blockDim.x) >> 5;
    int nact = g_nact;

    for (int i = gw; i < nact; i += nw) {
        int2 e = g_ec[i];
        float4 hv = *(const float4*)&g_T[(size_t)e.y * FEAT + lane * 4];
        float* dp = &g_accT[(size_t)e.x * FEAT + lane * 4];
        asm volatile("red.global.add.v4.f32 [%0], {%1,%2,%3,%4};"
                     :: "l"(dp), "f"(hv.x), "f"(hv.y), "f"(hv.z), "f"(hv.w)
                     : "memory");
    }
}

// ---------------------------------------------------------------------------
// GEMM2 (B rows only): out[i] = flag_i * ((accT[s_i]/cnt_i) @ W2 + b2).
// ---------------------------------------------------------------------------
__global__ __launch_bounds__(256)
void gemm2_kernel(const void* __restrict__ node_idx,
                  const float* __restrict__ W2,
                  const float* __restrict__ b2,
                  float* __restrict__ out,
                  int B)
{
    extern __shared__ float sm[];
    float* sW    = sm;
    float* sA    = sm + 16384;
    float* sFlag = sm + 16384 + 8192;

    int tid  = threadIdx.x;
    int i0   = blockIdx.x * 64;
    int is64 = g_is64;

    for (int i = tid * 4; i < 16384; i += 256 * 4)
        *(float4*)&sW[i] = *(const float4*)&W2[i];

    {
        int r = tid >> 2;
        int q = tid & 3;
        int i = i0 + r;
        float  scale = 0.f;
        size_t s = 0;
        int    c = 0;
        bool   valid = (i < B);
        if (valid) {
            long long sv = is64 ? ((const long long*)node_idx)[i]
                                : (long long)((const int*)node_idx)[i];
            if ((unsigned long long)sv < (unsigned long long)N_NODES) {
                s = (size_t)sv;
                c = g_cnt[s];
            } else valid = false;
            scale = (c > 0) ? (1.f / (float)c) : 0.f;
        }
        if (q == 0) sFlag[r] = (valid && c > 0) ? 1.f : 0.f;
        #pragma unroll
        for (int j = 0; j < 8; j++) {
            int col = q * 32 + j * 4;
            float4 v = make_float4(0.f, 0.f, 0.f, 0.f);
            if (valid) {
                v = *(const float4*)&g_accT[s * FEAT + col];
                v.x *= scale; v.y *= scale; v.z *= scale; v.w *= scale;
            }
            *(float4*)&sA[r * 128 + col] = v;
        }
    }
    __syncthreads();

    int tr = tid >> 5;
    int tc = tid & 31;

    float acc[8][4];
    #pragma unroll
    for (int r = 0; r < 8; r++)
        #pragma unroll
        for (int c = 0; c < 4; c++) acc[r][c] = 0.f;

    #pragma unroll 4
    for (int k = 0; k < 128; k += 4) {
        float4 p0 = *(const float4*)&sW[(k + 0) * 128 + tc * 4];
        float4 p1 = *(const float4*)&sW[(k + 1) * 128 + tc * 4];
        float4 p2 = *(const float4*)&sW[(k + 2) * 128 + tc * 4];
        float4 p3 = *(const float4*)&sW[(k + 3) * 128 + tc * 4];
        #pragma unroll
        for (int r = 0; r < 8; r++) {
            float4 a = *(const float4*)&sA[(tr * 8 + r) * 128 + k];
            acc[r][0] += a.x * p0.x + a.y * p1.x + a.z * p2.x + a.w * p3.x;
            acc[r][1] += a.x * p0.y + a.y * p1.y + a.z * p2.y + a.w * p3.y;
            acc[r][2] += a.x * p0.z + a.y * p1.z + a.z * p2.z + a.w * p3.z;
            acc[r][3] += a.x * p0.w + a.y * p1.w + a.z * p2.w + a.w * p3.w;
        }
    }

    float4 bias = *(const float4*)&b2[tc * 4];
    #pragma unroll
    for (int r = 0; r < 8; r++) {
        int rl = tr * 8 + r;
        int i  = i0 + rl;
        if (i < B) {
            float f = sFlag[rl];
            float4 o;
            o.x = f * (acc[r][0] + bias.x);
            o.y = f * (acc[r][1] + bias.y);
            o.z = f * (acc[r][2] + bias.z);
            o.w = f * (acc[r][3] + bias.w);
            *(float4*)&out[(size_t)i * FEAT + tc * 4] = o;
        }
    }
}

// ---------------------------------------------------------------------------
extern "C" void kernel_launch(void* const* d_in, const int* in_sizes, int n_in,
                              void* d_out, int out_size)
{
    const void*  edges    = d_in[0];
    const void*  node_idx = d_in[1];
    const float* X        = (const float*)d_in[2];
    const float* W1       = (const float*)d_in[3];
    const float* b1       = (const float*)d_in[4];
    const float* W2       = (const float*)d_in[5];
    const float* b2       = (const float*)d_in[6];
    const int*   ind      = (const int*)d_in[7];

    int E = in_sizes[0] / 2;
    int B = in_sizes[1];
    int N = in_sizes[2] / FEAT;
    float* out = (float*)d_out;

    void* p_needed;
    cudaGetSymbolAddress(&p_needed, g_needed);
    cudaMemsetAsync(p_needed, 0, N_NODES);

    cudaFuncSetAttribute(gemm1_mma_kernel, cudaFuncAttributeMaxDynamicSharedMemorySize, SM_TOT);
    cudaFuncSetAttribute(gemm2_kernel,     cudaFuncAttributeMaxDynamicSharedMemorySize, 98560);

    probe_kernel<<<1, 32>>>((const int*)edges, in_sizes[0]);
    mark_zero_kernel<<<(B * 32 + 255) / 256, 256>>>(node_idx, B);
    filter_kernel<<<(E + 255) / 256, 256>>>(edges, ind, E);
    wprep_kernel<<<64, 256>>>(W1);
    gemm1_mma_kernel<<<(N + 127) / 128, 256, SM_TOT>>>(X, b1, N);
    agg_kernel<<<1184, 256>>>();
    gemm2_kernel<<<(B + 63) / 64, 256, 98560>>>(node_idx, W2, b2, out, B);
}

// round 9
// speedup vs baseline: 1.5490x; 1.5490x over previous
#include <cuda_runtime.h>
#include <cuda_bf16.h>
#include <cstdint>
#include <cstddef>

#define N_NODES 50000
#define FEAT 128
#define E_MAX 800000
#define WSTRIDE 136   // bf16 elements per row in smem (272B = 17 * 16B -> conflict-free ldmatrix)

// ---------------- scratch (static device globals; no allocs) ----------------
__device__ __align__(16) unsigned char g_needed[N_NODES];
__device__ int                         g_cnt[N_NODES];
__device__ __align__(16) float         g_accT[(size_t)N_NODES * FEAT];
__device__ __align__(16) float         g_T[(size_t)N_NODES * FEAT];
__device__ int                         g_is64;
__device__ int                         g_nact;
__device__ __align__(8)  int2          g_ec[E_MAX];                 // compacted edges
__device__ __align__(16) unsigned short g_Whi[128 * WSTRIDE];       // W1^T hi, padded [n][k]
__device__ __align__(16) unsigned short g_Wlo[128 * WSTRIDE];       // W1^T lo, padded [n][k]

__device__ __forceinline__ uint32_t smem_u32(const void* p) {
    uint32_t a;
    asm("{ .reg .u64 t; cvta.to.shared.u64 t, %1; cvt.u32.u64 %0, t; }" : "=r"(a) : "l"(p));
    return a;
}

#define LDSM4(r, addr) \
    asm volatile("ldmatrix.sync.aligned.m8n8.x4.shared.b16 {%0,%1,%2,%3}, [%4];" \
        : "=r"((r)[0]), "=r"((r)[1]), "=r"((r)[2]), "=r"((r)[3]) : "r"(addr))

#define MMA16816(d, a, b0, b1) \
    asm volatile("mma.sync.aligned.m16n8k16.row.col.f32.bf16.bf16.f32 " \
        "{%0,%1,%2,%3}, {%4,%5,%6,%7}, {%8,%9}, {%0,%1,%2,%3};" \
        : "+f"((d)[0]), "+f"((d)[1]), "+f"((d)[2]), "+f"((d)[3]) \
        : "r"((a)[0]), "r"((a)[1]), "r"((a)[2]), "r"((a)[3]), "r"(b0), "r"(b1))

// ---------------------------------------------------------------------------
// Probe index dtype; also zero g_nact for this call.
// ---------------------------------------------------------------------------
__global__ void probe_kernel(const int* __restrict__ e, int nwords)
{
    int lane = threadIdx.x;
    int n = nwords < 2048 ? nwords : 2048;
    int any = 0;
    for (int i = 1 + 2 * lane; i < n; i += 64) any |= e[i];
    #pragma unroll
    for (int o = 16; o; o >>= 1) any |= __shfl_xor_sync(0xffffffffu, any, o);
    if (lane == 0) { g_is64 = (any == 0) ? 1 : 0; g_nact = 0; }
}

// ---------------------------------------------------------------------------
// Mark needed nodes + zero their cnt and accT row (one warp per node_idx).
// ---------------------------------------------------------------------------
__global__ __launch_bounds__(256)
void mark_zero_kernel(const void* __restrict__ node_idx, int B)
{
    int w    = (blockIdx.x * blockDim.x + threadIdx.x) >> 5;
    int lane = threadIdx.x & 31;
    if (w >= B) return;
    long long s = g_is64 ? ((const long long*)node_idx)[w]
                         : (long long)((const int*)node_idx)[w];
    if ((unsigned long long)s >= (unsigned long long)N_NODES) return;
    if (lane == 0) { g_needed[s] = 1; g_cnt[s] = 0; }
    *(float4*)&g_accT[(size_t)s * FEAT + lane * 4] = make_float4(0.f, 0.f, 0.f, 0.f);
}

// ---------------------------------------------------------------------------
// Filter + compact edges; count degrees for needed src.
// ---------------------------------------------------------------------------
__global__ __launch_bounds__(256)
void filter_kernel(const void* __restrict__ edges, const int* __restrict__ ind_ptr, int E)
{
    int i    = blockIdx.x * blockDim.x + threadIdx.x;
    int lane = threadIdx.x & 31;
    int is64 = g_is64;
    int keep_self = (*ind_ptr < 2);

    int src = 0, dst = 0;
    bool act = false;
    if (i < E) {
        if (is64) { longlong2 p = ((const longlong2*)edges)[i]; src = (int)p.x; dst = (int)p.y; }
        else      { int2 p = ((const int2*)edges)[i];           src = p.x;      dst = p.y; }
        act = ((src != dst) | keep_self)
              && ((unsigned)src < (unsigned)N_NODES)
              && ((unsigned)dst < (unsigned)N_NODES)
              && g_needed[src];
    }
    unsigned m = __ballot_sync(0xffffffffu, act);
    int cnt = __popc(m);
    int base = 0;
    if (lane == 0 && cnt) base = atomicAdd(&g_nact, cnt);
    base = __shfl_sync(0xffffffffu, base, 0);
    if (act) {
        int off = __popc(m & ((1u << lane) - 1u));
        g_ec[base + off] = make_int2(src, dst);
        atomicAdd(&g_cnt[src], 1);
    }
}

// ---------------------------------------------------------------------------
// W prep: W1^T split into bf16 hi/lo, padded [n][WSTRIDE] k-major layout.
// Coalesced: adjacent threads read adjacent W1 words (same k-row).
// ---------------------------------------------------------------------------
__global__ void wprep_kernel(const float* __restrict__ W1)
{
    int idx = blockIdx.x * blockDim.x + threadIdx.x;
    if (idx >= 16384) return;
    int k = idx >> 7, n = idx & 127;          // coalesced read of W1[k][n]
    float w = W1[k * 128 + n];
    __nv_bfloat16 hi = __float2bfloat16(w);
    __nv_bfloat16 lo = __float2bfloat16(w - __bfloat162float(hi));
    unsigned short hs, ls;
    *(__nv_bfloat16*)&hs = hi;
    *(__nv_bfloat16*)&ls = lo;
    g_Whi[n * WSTRIDE + k] = hs;
    g_Wlo[n * WSTRIDE + k] = ls;
}

// ---------------------------------------------------------------------------
// GEMM1 via mma.sync (HMMA bf16, 3-pass split): T = tanh(X @ W1 + b1).
// CTA: 256 threads / 8 warps; tile 128 rows x 128 cols; K=128 in smem.
// Warp w owns rows w*16 .. w*16+15 (full 128 cols).
// Mainloop kept SMALL (no mega-unroll) to stay in L0 I-cache and avoid spills.
// ---------------------------------------------------------------------------
#define SM_XHI 0
#define SM_XLO (SM_XHI + 128 * WSTRIDE * 2)
#define SM_WHI (SM_XLO + 128 * WSTRIDE * 2)
#define SM_WLO (SM_WHI + 128 * WSTRIDE * 2)
#define SM_TOT (SM_WLO + 128 * WSTRIDE * 2)

__global__ __launch_bounds__(256)
void gemm1_mma_kernel(const float* __restrict__ X,
                      const float* __restrict__ b1,
                      int Nrows)
{
    extern __shared__ char smem[];
    uint32_t sb  = smem_u32(smem);
    int tid  = threadIdx.x;
    int wid  = tid >> 5;
    int lane = tid & 31;
    int row0 = blockIdx.x * 128;

    // --- copy pre-split W images (linear, 16B chunks; 34816B each) ---
    for (int i = tid * 16; i < 128 * WSTRIDE * 2; i += 256 * 16) {
        *(uint4*)(smem + SM_WHI + i) = *(const uint4*)((const char*)g_Whi + i);
        *(uint4*)(smem + SM_WLO + i) = *(const uint4*)((const char*)g_Wlo + i);
    }

    // --- convert X tile fp32 -> bf16 hi/lo, padded [row][WSTRIDE] ---
    {
        int r    = tid >> 1;
        int half = (tid & 1) * 64;
        int gr   = row0 + r;
        const float* xr = X + (size_t)gr * FEAT;
        #pragma unroll
        for (int j = 0; j < 8; j++) {
            int c0 = half + j * 8;
            float4 v0 = make_float4(0.f, 0.f, 0.f, 0.f), v1 = v0;
            if (gr < Nrows) {
                v0 = *(const float4*)&xr[c0];
                v1 = *(const float4*)&xr[c0 + 4];
            }
            float xs[8] = {v0.x, v0.y, v0.z, v0.w, v1.x, v1.y, v1.z, v1.w};
            unsigned hi[4], lo[4];
            #pragma unroll
            for (int q = 0; q < 4; q++) {
                float a = xs[2 * q], b = xs[2 * q + 1];
                __nv_bfloat162 h = __floats2bfloat162_rn(a, b);
                float2 hf = __bfloat1622float2(h);
                __nv_bfloat162 l = __floats2bfloat162_rn(a - hf.x, b - hf.y);
                hi[q] = *(unsigned*)&h;
                lo[q] = *(unsigned*)&l;
            }
            int off = (r * WSTRIDE + c0) * 2;   // 16B aligned (272*r + 16*j')
            *(uint4*)(smem + SM_XHI + off) = make_uint4(hi[0], hi[1], hi[2], hi[3]);
            *(uint4*)(smem + SM_XLO + off) = make_uint4(lo[0], lo[1], lo[2], lo[3]);
        }
    }
    __syncthreads();

    // --- fragment address bases ---
    int sub = lane >> 3, rr = lane & 7;
    int a_m = wid * 16 + (sub & 1) * 8 + rr;
    int a_k = (sub >> 1) * 8;
    uint32_t aOff = (uint32_t)((a_m * WSTRIDE + a_k) * 2);
    int b_n = (sub >> 1) * 8 + rr;
    int b_k = (sub & 1) * 8;
    uint32_t bOff = (uint32_t)((b_n * WSTRIDE + b_k) * 2);

    float d[16][4];
    #pragma unroll
    for (int j = 0; j < 16; j++)
        #pragma unroll
        for (int q = 0; q < 4; q++) d[j][q] = 0.f;

    #pragma unroll 1
    for (int pass = 0; pass < 3; pass++) {
        uint32_t aBase = sb + ((pass < 2)  ? SM_XHI : SM_XLO) + aOff;
        uint32_t bBase = sb + ((pass == 1) ? SM_WLO : SM_WHI) + bOff;
        #pragma unroll 2
        for (int ks = 0; ks < 8; ks++) {
            uint32_t a[4];
            LDSM4(a, aBase + (uint32_t)ks * 32);          // k0 = ks*16 -> 32 bytes
            uint32_t bAddr = bBase + (uint32_t)ks * 32;
            #pragma unroll
            for (int np = 0; np < 8; np++) {
                uint32_t b[4];
                LDSM4(b, bAddr + (uint32_t)(np * 16 * WSTRIDE * 2));
                MMA16816(d[np * 2],     a, b[0], b[1]);
                MMA16816(d[np * 2 + 1], a, b[2], b[3]);
            }
        }
    }

    // --- epilogue: bias + tanh, store to g_T ---
    {
        int g = lane >> 2, c = lane & 3;
        int m0 = wid * 16 + g;
        int gr0 = row0 + m0, gr1 = gr0 + 8;
        #pragma unroll
        for (int j = 0; j < 16; j++) {
            int col = j * 8 + c * 2;
            float bx = b1[col], by = b1[col + 1];
            if (gr0 < Nrows) {
                float2 o;
                o.x = tanhf(d[j][0] + bx);
                o.y = tanhf(d[j][1] + by);
                *(float2*)&g_T[(size_t)gr0 * FEAT + col] = o;
            }
            if (gr1 < Nrows) {
                float2 o;
                o.x = tanhf(d[j][2] + bx);
                o.y = tanhf(d[j][3] + by);
                *(float2*)&g_T[(size_t)gr1 * FEAT + col] = o;
            }
        }
    }
}

// ---------------------------------------------------------------------------
// Aggregate compacted edges: one warp per edge; lane handles 4 floats.
// ---------------------------------------------------------------------------
__global__ __launch_bounds__(256)
void agg_kernel()
{
    int gw   = (blockIdx.x * blockDim.x + threadIdx.x) >> 5;
    int lane = threadIdx.x & 31;
    int nw   = (gridDim.x * blockDim.x) >> 5;
    int nact = g_nact;

    for (int i = gw; i < nact; i += nw) {
        int2 e = g_ec[i];
        float4 hv = *(const float4*)&g_T[(size_t)e.y * FEAT + lane * 4];
        float* dp = &g_accT[(size_t)e.x * FEAT + lane * 4];
        asm volatile("red.global.add.v4.f32 [%0], {%1,%2,%3,%4};"
                     :: "l"(dp), "f"(hv.x), "f"(hv.y), "f"(hv.z), "f"(hv.w)
                     : "memory");
    }
}

// ---------------------------------------------------------------------------
// GEMM2 (B rows only): out[i] = flag_i * ((accT[s_i]/cnt_i) @ W2 + b2).
// ---------------------------------------------------------------------------
__global__ __launch_bounds__(256)
void gemm2_kernel(const void* __restrict__ node_idx,
                  const float* __restrict__ W2,
                  const float* __restrict__ b2,
                  float* __restrict__ out,
                  int B)
{
    extern __shared__ float sm[];
    float* sW    = sm;
    float* sA    = sm + 16384;
    float* sFlag = sm + 16384 + 8192;

    int tid  = threadIdx.x;
    int i0   = blockIdx.x * 64;
    int is64 = g_is64;

    for (int i = tid * 4; i < 16384; i += 256 * 4)
        *(float4*)&sW[i] = *(const float4*)&W2[i];

    {
        int r = tid >> 2;
        int q = tid & 3;
        int i = i0 + r;
        float  scale = 0.f;
        size_t s = 0;
        int    c = 0;
        bool   valid = (i < B);
        if (valid) {
            long long sv = is64 ? ((const long long*)node_idx)[i]
                                : (long long)((const int*)node_idx)[i];
            if ((unsigned long long)sv < (unsigned long long)N_NODES) {
                s = (size_t)sv;
                c = g_cnt[s];
            } else valid = false;
            scale = (c > 0) ? (1.f / (float)c) : 0.f;
        }
        if (q == 0) sFlag[r] = (valid && c > 0) ? 1.f : 0.f;
        #pragma unroll
        for (int j = 0; j < 8; j++) {
            int col = q * 32 + j * 4;
            float4 v = make_float4(0.f, 0.f, 0.f, 0.f);
            if (valid) {
                v = *(const float4*)&g_accT[s * FEAT + col];
                v.x *= scale; v.y *= scale; v.z *= scale; v.w *= scale;
            }
            *(float4*)&sA[r * 128 + col] = v;
        }
    }
    __syncthreads();

    int tr = tid >> 5;
    int tc = tid & 31;

    float acc[8][4];
    #pragma unroll
    for (int r = 0; r < 8; r++)
        #pragma unroll
        for (int c = 0; c < 4; c++) acc[r][c] = 0.f;

    #pragma unroll 4
    for (int k = 0; k < 128; k += 4) {
        float4 p0 = *(const float4*)&sW[(k + 0) * 128 + tc * 4];
        float4 p1 = *(const float4*)&sW[(k + 1) * 128 + tc * 4];
        float4 p2 = *(const float4*)&sW[(k + 2) * 128 + tc * 4];
        float4 p3 = *(const float4*)&sW[(k + 3) * 128 + tc * 4];
        #pragma unroll
        for (int r = 0; r < 8; r++) {
            float4 a = *(const float4*)&sA[(tr * 8 + r) * 128 + k];
            acc[r][0] += a.x * p0.x + a.y * p1.x + a.z * p2.x + a.w * p3.x;
            acc[r][1] += a.x * p0.y + a.y * p1.y + a.z * p2.y + a.w * p3.y;
            acc[r][2] += a.x * p0.z + a.y * p1.z + a.z * p2.z + a.w * p3.z;
            acc[r][3] += a.x * p0.w + a.y * p1.w + a.z * p2.w + a.w * p3.w;
        }
    }

    float4 bias = *(const float4*)&b2[tc * 4];
    #pragma unroll
    for (int r = 0; r < 8; r++) {
        int rl = tr * 8 + r;
        int i  = i0 + rl;
        if (i < B) {
            float f = sFlag[rl];
            float4 o;
            o.x = f * (acc[r][0] + bias.x);
            o.y = f * (acc[r][1] + bias.y);
            o.z = f * (acc[r][2] + bias.z);
            o.w = f * (acc[r][3] + bias.w);
            *(float4*)&out[(size_t)i * FEAT + tc * 4] = o;
        }
    }
}

// ---------------------------------------------------------------------------
extern "C" void kernel_launch(void* const* d_in, const int* in_sizes, int n_in,
                              void* d_out, int out_size)
{
    const void*  edges    = d_in[0];
    const void*  node_idx = d_in[1];
    const float* X        = (const float*)d_in[2];
    const float* W1       = (const float*)d_in[3];
    const float* b1       = (const float*)d_in[4];
    const float* W2       = (const float*)d_in[5];
    const float* b2       = (const float*)d_in[6];
    const int*   ind      = (const int*)d_in[7];

    int E = in_sizes[0] / 2;
    int B = in_sizes[1];
    int N = in_sizes[2] / FEAT;
    float* out = (float*)d_out;

    void* p_needed;
    cudaGetSymbolAddress(&p_needed, g_needed);
    cudaMemsetAsync(p_needed, 0, N_NODES);

    cudaFuncSetAttribute(gemm1_mma_kernel, cudaFuncAttributeMaxDynamicSharedMemorySize, SM_TOT);
    cudaFuncSetAttribute(gemm2_kernel,     cudaFuncAttributeMaxDynamicSharedMemorySize, 98560);

    probe_kernel<<<1, 32>>>((const int*)edges, in_sizes[0]);
    mark_zero_kernel<<<(B * 32 + 255) / 256, 256>>>(node_idx, B);
    filter_kernel<<<(E + 255) / 256, 256>>>(edges, ind, E);
    wprep_kernel<<<64, 256>>>(W1);
    gemm1_mma_kernel<<<(N + 127) / 128, 256, SM_TOT>>>(X, b1, N);
    agg_kernel<<<1184, 256>>>();
    gemm2_kernel<<<(B + 63) / 64, 256, 98560>>>(node_idx, W2, b2, out, B);
}